// round 15
// baseline (speedup 1.0000x reference)
#include <cuda_runtime.h>
#include <cuda_bf16.h>
#include <cuda_fp16.h>

#define SEQ   512
#define T_LEN 65536
#define NN    131072
#define NHALF 65536
#define N2    2048

// Scratch (device globals; no allocations allowed)
__device__ __half2 g_zh[(size_t)SEQ * NN];      // 256 MiB fp16 stage1->2 buffer
__device__ __half2 g_h[(size_t)SEQ * 33 * N2];  // 138 MiB fp16 stage2->3 buffer
__device__ float2 g_tw[NN];                     // g_tw[h+p] = exp(-i*pi*p/h)

static __device__ __forceinline__ float2 cmul(float2 a, float2 b) {
    return make_float2(fmaf(a.x, b.x, -a.y * b.y), fmaf(a.x, b.y, a.y * b.x));
}
static __device__ __forceinline__ float2 cadd(float2 a, float2 b) { return make_float2(a.x+b.x, a.y+b.y); }
static __device__ __forceinline__ float2 csub(float2 a, float2 b) { return make_float2(a.x-b.x, a.y-b.y); }
static __device__ __forceinline__ float2 mulnI(float2 a) { return make_float2(a.y, -a.x); }   // * (-i)
static __device__ __forceinline__ float2 mulpI(float2 a) { return make_float2(-a.y, a.x); }   // * (+i)
static __device__ __forceinline__ float2 cconj(float2 a) { return make_float2(a.x, -a.y); }

// W_{2*Mhalf}^q  for q in [0, 2*Mhalf)
static __device__ __forceinline__ float2 twid(int Mhalf, int q) {
    if (q < Mhalf) return g_tw[Mhalf + q];
    float2 t = g_tw[q];                    // == g_tw[Mhalf + (q - Mhalf)]
    return make_float2(-t.x, -t.y);
}
// conj(W_{2*Mhalf}^q)
static __device__ __forceinline__ float2 twidc(int Mhalf, int q) {
    if (q < Mhalf) { float2 t = g_tw[Mhalf + q]; return make_float2(t.x, -t.y); }
    float2 t = g_tw[q];
    return make_float2(-t.x, t.y);
}

// Powers W[j] = w^j, j=1..7, built with a depth-3 tree (6 cmuls, 1 load).
static __device__ __forceinline__ void twpow(float2 W[8], float2 w) {
    W[1] = w;
    W[2] = cmul(w, w);
    W[3] = cmul(W[2], w);
    W[4] = cmul(W[2], W[2]);
    W[5] = cmul(W[2], W[3]);
    W[6] = cmul(W[3], W[3]);
    W[7] = cmul(W[3], W[4]);
}

// 8-pt DFT, natural in/out. INV => conjugated twiddles (unnormalized inverse).
template<bool INV>
static __device__ __forceinline__ void fft8(float2 z[8]) {
    const float C = 0.70710678118654752440f;
    float2 t0=cadd(z[0],z[4]), t1=cadd(z[1],z[5]), t2=cadd(z[2],z[6]), t3=cadd(z[3],z[7]);
    float2 s0=csub(z[0],z[4]), s1=csub(z[1],z[5]), s2=csub(z[2],z[6]), s3=csub(z[3],z[7]);
    if (!INV) {
        s1 = cmul(s1, make_float2(C,-C)); s2 = mulnI(s2); s3 = cmul(s3, make_float2(-C,-C));
    } else {
        s1 = cmul(s1, make_float2(C, C)); s2 = mulpI(s2); s3 = cmul(s3, make_float2(-C, C));
    }
    float2 a0=cadd(t0,t2), a1=csub(t0,t2), a2=cadd(t1,t3), a3=csub(t1,t3);
    a3 = INV ? mulpI(a3) : mulnI(a3);
    float2 b0=cadd(s0,s2), b1=csub(s0,s2), b2=cadd(s1,s3), b3=csub(s1,s3);
    b3 = INV ? mulpI(b3) : mulnI(b3);
    z[0]=cadd(a0,a2); z[4]=csub(a0,a2);
    z[2]=cadd(a1,a3); z[6]=csub(a1,a3);
    z[1]=cadd(b0,b2); z[5]=csub(b0,b2);
    z[3]=cadd(b1,b3); z[7]=csub(b1,b3);
}

template<bool INV>
static __device__ __forceinline__ void fft4(float2 z[4]) {
    float2 a0=cadd(z[0],z[2]), a1=csub(z[0],z[2]);
    float2 a2=cadd(z[1],z[3]), a3=csub(z[1],z[3]);
    a3 = INV ? mulpI(a3) : mulnI(a3);
    z[0]=cadd(a0,a2); z[2]=csub(a0,a2);
    z[1]=cadd(a1,a3); z[3]=csub(a1,a3);
}

// 16-pt DFT, natural in/out, via 4x4 Cooley-Tukey. INV => conj twiddles.
template<bool INV>
static __device__ __forceinline__ void fft16(float2 z[16]) {
    const float C1 = 0.92387953251128675613f;   // cos(pi/8)
    const float S1 = 0.38268343236508977173f;   // sin(pi/8)
    const float R  = 0.70710678118654752440f;
    const float2 W1 = INV ? make_float2(C1,  S1) : make_float2(C1, -S1);
    const float2 W2 = INV ? make_float2(R,   R ) : make_float2(R,  -R );
    const float2 W3 = INV ? make_float2(S1,  C1) : make_float2(S1, -C1);
    const float2 W6 = INV ? make_float2(-R,  R ) : make_float2(-R, -R );
    const float2 W9 = INV ? make_float2(-C1,-S1) : make_float2(-C1, S1);
    float2 t[16];
    #pragma unroll
    for (int b = 0; b < 4; b++) {
        float2 q[4] = { z[b], z[4+b], z[8+b], z[12+b] };
        fft4<INV>(q);
        if (b == 1) { q[1]=cmul(q[1],W1); q[2]=cmul(q[2],W2); q[3]=cmul(q[3],W3); }
        if (b == 2) { q[1]=cmul(q[1],W2); q[2]= INV?mulpI(q[2]):mulnI(q[2]); q[3]=cmul(q[3],W6); }
        if (b == 3) { q[1]=cmul(q[1],W3); q[2]=cmul(q[2],W6); q[3]=cmul(q[3],W9); }
        t[b] = q[0]; t[4+b] = q[1]; t[8+b] = q[2]; t[12+b] = q[3];
    }
    #pragma unroll
    for (int c = 0; c < 4; c++) {
        float2 q[4] = { t[4*c+0], t[4*c+1], t[4*c+2], t[4*c+3] };
        fft4<INV>(q);
        z[c] = q[0]; z[c+4] = q[1]; z[c+8] = q[2]; z[c+12] = q[3];
    }
}

// Hermitian unpack + pointwise: Za = Z[k], Zb = Z[N-k]; returns Y[k] = X[k]*H[k]
static __device__ __forceinline__ float2 pw(float2 Za, float2 Zb) {
    float2 X = make_float2(0.5f*(Za.x+Zb.x),  0.5f*(Za.y-Zb.y));
    float2 H = make_float2(0.5f*(Za.y+Zb.y), -0.5f*(Za.x-Zb.x));
    return cmul(X, H);
}

#define PAD(p) ((p) + (((p) >> 5) << 2))
// digit-reversed position for plan 16(str128),16(str8),8(str1):
// k2 = j + 16*j2 + 256*j3  ->  p = 128*j + 8*j2 + j3
#define POS16(k2) ((((k2) & 15) << 7) + ((((k2) >> 4) & 15) << 3) + ((k2) >> 8))

__global__ void k_init_tw() {
    int idx = blockIdx.x * blockDim.x + threadIdx.x;
    if (idx >= NN) return;
    if (idx == 0) { g_tw[0] = make_float2(1.0f, 0.0f); return; }
    int h = 1 << (31 - __clz(idx));
    int p = idx - h;
    float s, c;
    sincospif(-(float)p / (float)h, &s, &c);
    g_tw[idx] = make_float2(c, s);
}

// ---------------------------------------------------------------------------
// Stage 1: pack z = bf16(x) + i*h (rows n1>=32 are zero) + 64-pt FFT along n1
// (two register radix-8 passes, one smem exchange) + twiddle W_N^{k1*n2}.
// Output (fp16): g_zh[s][k1*2048 + n2]
// ---------------------------------------------------------------------------
__global__ void __launch_bounds__(256) k_stage1(const float* __restrict__ x,
                                                const float* __restrict__ hk) {
    __shared__ float2 sm[64 * 32];
    const int s   = blockIdx.y;
    const int col = threadIdx.x & 31;
    const int a   = threadIdx.x >> 5;          // 0..7
    const int n2  = blockIdx.x * 32 + col;
    const float* xs = x  + (size_t)s * T_LEN;
    const float* hs = hk + (size_t)s * T_LEN;

    float2 v[8];
    #pragma unroll
    for (int b = 0; b < 4; b++) {
        int n = (a + 8*b) * N2 + n2;           // < 65536 always
        v[b] = make_float2(__bfloat162float(__float2bfloat16_rn(xs[n])), hs[n]);
    }
    // fft8 over b with upper half zero (t = z, s = z)
    {
        const float C = 0.70710678118654752440f;
        float2 t0=v[0], t1=v[1], t2=v[2], t3=v[3];
        float2 s0=v[0];
        float2 s1=cmul(v[1], make_float2(C,-C));
        float2 s2=mulnI(v[2]);
        float2 s3=cmul(v[3], make_float2(-C,-C));
        float2 a0=cadd(t0,t2), a1=csub(t0,t2), a2=cadd(t1,t3), a3=mulnI(csub(t1,t3));
        float2 b0=cadd(s0,s2), b1=csub(s0,s2), b2=cadd(s1,s3), b3=mulnI(csub(s1,s3));
        v[0]=cadd(a0,a2); v[4]=csub(a0,a2);
        v[2]=cadd(a1,a3); v[6]=csub(a1,a3);
        v[1]=cadd(b0,b2); v[5]=csub(b0,b2);
        v[3]=cadd(b1,b3); v[7]=csub(b1,b3);
    }
    // twiddle W_64^{a*j}
    {
        float2 W[8];
        twpow(W, twid(32, a));
        #pragma unroll
        for (int j = 1; j < 8; j++) v[j] = cmul(v[j], W[j]);
    }
    #pragma unroll
    for (int j = 0; j < 8; j++) sm[(j*8 + a)*32 + col] = v[j];
    __syncthreads();

    const int j = a;                            // phase-2 role
    #pragma unroll
    for (int q = 0; q < 8; q++) v[q] = sm[(j*8 + q)*32 + col];
    fft8<false>(v);                             // over a -> m ; k1 = j + 8m

    __half2* zs = g_zh + (size_t)s * NN;
    {
        float2 acc  = twid(NHALF, n2 * j);      // n2*j < 65536
        float2 step = twid(NHALF, 8 * n2);
        #pragma unroll
        for (int m = 0; m < 8; m++) {
            int k1 = j + 8*m;
            float2 y = cmul(v[m], acc);
            zs[k1 * N2 + n2] = __floats2half2_rn(y.x, y.y);
            acc = cmul(acc, step);
        }
    }
}

// ---------------------------------------------------------------------------
// Stage 2 (radix-16 plan 2048 = 16x16x8, 256 threads, 3 blocks/SM):
// pair {g, 64-g} ({0,32} for g==0). Twiddle loops use 4 interleaved chains
// (depth ~5 instead of 15) to keep the 16 smem ops per loop pipelined.
// ---------------------------------------------------------------------------
__global__ void __launch_bounds__(256, 3) k_stage2() {
    __shared__ float2 smA[2304];
    __shared__ float2 smB[2304];
    const int s = blockIdx.y;
    const int g = blockIdx.x;                   // 0..31
    const int rowA = g;
    const int rowB = (g == 0) ? 32 : 64 - g;
    const int u = threadIdx.x;                  // 0..255
    const __half2* zb = g_zh + (size_t)s * NN;

    float2 v[16];

    // ---- S1: radix-16 over stride 128, twiddle W_2048^{c*j} ----
    {
        const int r = u >> 7, c = u & 127;
        const __half2* glob = zb + (r ? rowB : rowA) * N2;
        float2* sm = r ? smB : smA;
        #pragma unroll
        for (int t = 0; t < 16; t++) v[t] = __half22float2(glob[c + 128*t]);
        fft16<false>(v);
        float2 w1 = twid(1024, c);
        float2 w2 = cmul(w1, w1), w3 = cmul(w2, w1), w4 = cmul(w2, w2);
        sm[PAD(c)]          = v[0];
        sm[PAD(128*1 + c)]  = cmul(v[1], w1);
        sm[PAD(128*2 + c)]  = cmul(v[2], w2);
        sm[PAD(128*3 + c)]  = cmul(v[3], w3);
        float2 a0 = w4, a1 = cmul(w1, w4), a2 = cmul(w2, w4), a3 = cmul(w3, w4);
        #pragma unroll
        for (int rr4 = 1; rr4 < 4; rr4++) {
            sm[PAD(128*(4*rr4+0) + c)] = cmul(v[4*rr4+0], a0);
            sm[PAD(128*(4*rr4+1) + c)] = cmul(v[4*rr4+1], a1);
            sm[PAD(128*(4*rr4+2) + c)] = cmul(v[4*rr4+2], a2);
            sm[PAD(128*(4*rr4+3) + c)] = cmul(v[4*rr4+3], a3);
            if (rr4 < 3) { a0=cmul(a0,w4); a1=cmul(a1,w4); a2=cmul(a2,w4); a3=cmul(a3,w4); }
        }
    }
    __syncthreads();

    // ---- S2: radix-16 over stride 8, twiddle W_128^{e*j2} ----
    {
        const int r = u >> 7, idx = u & 127, j = idx >> 3, e = idx & 7;
        float2* sm = r ? smB : smA;
        const int base = 128*j + e;
        #pragma unroll
        for (int t2 = 0; t2 < 16; t2++) v[t2] = sm[PAD(base + 8*t2)];
        fft16<false>(v);
        float2 w1 = twid(64, e);
        float2 w2 = cmul(w1, w1), w3 = cmul(w2, w1), w4 = cmul(w2, w2);
        sm[PAD(base)]          = v[0];
        sm[PAD(base + 8*1)]    = cmul(v[1], w1);
        sm[PAD(base + 8*2)]    = cmul(v[2], w2);
        sm[PAD(base + 8*3)]    = cmul(v[3], w3);
        float2 a0 = w4, a1 = cmul(w1, w4), a2 = cmul(w2, w4), a3 = cmul(w3, w4);
        #pragma unroll
        for (int rr4 = 1; rr4 < 4; rr4++) {
            sm[PAD(base + 8*(4*rr4+0))] = cmul(v[4*rr4+0], a0);
            sm[PAD(base + 8*(4*rr4+1))] = cmul(v[4*rr4+1], a1);
            sm[PAD(base + 8*(4*rr4+2))] = cmul(v[4*rr4+2], a2);
            sm[PAD(base + 8*(4*rr4+3))] = cmul(v[4*rr4+3], a3);
            if (rr4 < 3) { a0=cmul(a0,w4); a1=cmul(a1,w4); a2=cmul(a2,w4); a3=cmul(a3,w4); }
        }
    }
    __syncthreads();

    if (g != 0) {
        // FUSED S3 fwd (A and B) + pointwise + IS3, all in registers.
        // A position p = 8u + j3 pairs with B position 2047-p = 8(255-u)+(7-j3).
        float2 a8[8], b8[8];
        #pragma unroll
        for (int e = 0; e < 8; e++) {
            a8[e] = smA[PAD(8*u + e)];
            b8[e] = smB[PAD(8*(255 - u) + e)];
        }
        fft8<false>(a8);
        fft8<false>(b8);
        float2 ya[8];
        #pragma unroll
        for (int j3 = 0; j3 < 8; j3++) ya[j3] = pw(a8[j3], b8[7 - j3]);
        fft8<true>(ya);
        #pragma unroll
        for (int e = 0; e < 8; e++) smA[PAD(8*u + e)] = ya[e];
    } else {
        // g==0: S3 forward both rows (in place per thread block-of-8)
        #pragma unroll
        for (int r = 0; r < 2; r++) {
            float2* sm = r ? smB : smA;
            float2 s8[8];
            #pragma unroll
            for (int e = 0; e < 8; e++) s8[e] = sm[PAD(8*u + e)];
            fft8<false>(s8);
            #pragma unroll
            for (int j3 = 0; j3 < 8; j3++) sm[PAD(8*u + j3)] = s8[j3];
        }
        __syncthreads();
        // row 0: pairs k2 <-> (2048-k2) mod 2048 (explicit POS16)
        #pragma unroll
        for (int e = 0; e < 4; e++) {
            int k2 = 4*u + e;                    // 0..1023
            int pa = POS16(k2);
            int pb = POS16((2048 - k2) & 2047);
            float2 Za = smA[PAD(pa)];
            float2 Zb = smA[PAD(pb)];
            float2 Y = pw(Za, Zb);
            smA[PAD(pa)] = Y;
            smA[PAD(pb)] = cconj(Y);
        }
        if (u == 0) {                            // k2 = 1024 self-pair
            int pa = POS16(1024);
            float2 Za = smA[PAD(pa)];
            smA[PAD(pa)] = pw(Za, Za);
        }
        // row 32: position-local p <-> 2047-p
        #pragma unroll
        for (int e = 0; e < 4; e++) {
            int p = 4*u + e;                     // 0..1023
            float2 Za = smB[PAD(p)];
            float2 Zb = smB[PAD(2047 - p)];
            float2 Y = pw(Za, Zb);
            smB[PAD(p)]        = Y;
            smB[PAD(2047 - p)] = cconj(Y);
        }
        __syncthreads();
        // IS3 both rows
        #pragma unroll
        for (int r = 0; r < 2; r++) {
            float2* sm = r ? smB : smA;
            float2 s8[8];
            #pragma unroll
            for (int j3 = 0; j3 < 8; j3++) s8[j3] = sm[PAD(8*u + j3)];
            fft8<true>(s8);
            #pragma unroll
            for (int e = 0; e < 8; e++) sm[PAD(8*u + e)] = s8[e];
        }
    }
    __syncthreads();

    const int rI = u >> 7, idxI = u & 127;
    const bool act = (rI == 0) || (g == 0);
    float2* smI = rI ? smB : smA;
    const int rowI = rI ? rowB : rowA;

    // ---- IS2: conj twiddle W_128^{-e*j2} (input side), inverse radix-16 ----
    // In-place safe: writes have low3 bits == e, only read by the same thread.
    if (act) {
        const int j = idxI >> 3, e = idxI & 7;
        const int base = 128*j + e;
        float2 w1 = twidc(64, e);
        float2 w2 = cmul(w1, w1), w3 = cmul(w2, w1), w4 = cmul(w2, w2);
        v[0] = smI[PAD(base)];
        v[1] = cmul(smI[PAD(base + 8*1)], w1);
        v[2] = cmul(smI[PAD(base + 8*2)], w2);
        v[3] = cmul(smI[PAD(base + 8*3)], w3);
        float2 a0 = w4, a1 = cmul(w1, w4), a2 = cmul(w2, w4), a3 = cmul(w3, w4);
        #pragma unroll
        for (int rr4 = 1; rr4 < 4; rr4++) {
            v[4*rr4+0] = cmul(smI[PAD(base + 8*(4*rr4+0))], a0);
            v[4*rr4+1] = cmul(smI[PAD(base + 8*(4*rr4+1))], a1);
            v[4*rr4+2] = cmul(smI[PAD(base + 8*(4*rr4+2))], a2);
            v[4*rr4+3] = cmul(smI[PAD(base + 8*(4*rr4+3))], a3);
            if (rr4 < 3) { a0=cmul(a0,w4); a1=cmul(a1,w4); a2=cmul(a2,w4); a3=cmul(a3,w4); }
        }
        fft16<true>(v);
        #pragma unroll
        for (int t2 = 0; t2 < 16; t2++) smI[PAD(base + 8*t2)] = v[t2];
    }
    __syncthreads();

    // ---- IS1: conj twiddle W_2048^{-c*j}, inverse radix-16, inter-twiddle
    //      W_N^{-row*(c+128t)} with 1/N folded, store fp16 ----
    if (act) {
        const int c = idxI;
        float2 w1 = twidc(1024, c);
        float2 w2 = cmul(w1, w1), w3 = cmul(w2, w1), w4 = cmul(w2, w2);
        v[0] = smI[PAD(c)];
        v[1] = cmul(smI[PAD(128*1 + c)], w1);
        v[2] = cmul(smI[PAD(128*2 + c)], w2);
        v[3] = cmul(smI[PAD(128*3 + c)], w3);
        float2 a0 = w4, a1 = cmul(w1, w4), a2 = cmul(w2, w4), a3 = cmul(w3, w4);
        #pragma unroll
        for (int rr4 = 1; rr4 < 4; rr4++) {
            v[4*rr4+0] = cmul(smI[PAD(128*(4*rr4+0) + c)], a0);
            v[4*rr4+1] = cmul(smI[PAD(128*(4*rr4+1) + c)], a1);
            v[4*rr4+2] = cmul(smI[PAD(128*(4*rr4+2) + c)], a2);
            v[4*rr4+3] = cmul(smI[PAD(128*(4*rr4+3) + c)], a3);
            if (rr4 < 3) { a0=cmul(a0,w4); a1=cmul(a1,w4); a2=cmul(a2,w4); a3=cmul(a3,w4); }
        }
        fft16<true>(v);
        const float SC = 1.0f / (float)NN;
        float2 b0 = twidc(NHALF, rowI * c);      // rowI*c <= 32*127 < 65536
        b0.x *= SC; b0.y *= SC;
        float2 st  = twidc(NHALF, 128 * rowI);   // <= 4096
        float2 st2 = cmul(st, st), st4 = cmul(st2, st2);
        float2 b1 = cmul(b0, st), b2 = cmul(b0, st2), b3 = cmul(b1, st2);
        __half2* gh = g_h + (size_t)s * (33 * N2) + rowI * N2;
        #pragma unroll
        for (int rr4 = 0; rr4 < 4; rr4++) {
            float2 y0 = cmul(v[4*rr4+0], b0);
            float2 y1 = cmul(v[4*rr4+1], b1);
            float2 y2 = cmul(v[4*rr4+2], b2);
            float2 y3 = cmul(v[4*rr4+3], b3);
            gh[c + 128*(4*rr4+0)] = __floats2half2_rn(y0.x, y0.y);
            gh[c + 128*(4*rr4+1)] = __floats2half2_rn(y1.x, y1.y);
            gh[c + 128*(4*rr4+2)] = __floats2half2_rn(y2.x, y2.y);
            gh[c + 128*(4*rr4+3)] = __floats2half2_rn(y3.x, y3.y);
            if (rr4 < 3) { b0=cmul(b0,st4); b1=cmul(b1,st4); b2=cmul(b2,st4); b3=cmul(b3,st4); }
        }
    }
}

// ---------------------------------------------------------------------------
// Stage 3 (real-output half-size IFFT): per column n2, build
//   G[k] = (U[k] + conj(U[32-k])) + i*w^k*(U[k] - conj(U[32-k])), w=e^{2pi i/64}
// from U rows 0..32 (fp16), then z = IFFT_32(G): y[2n]=Re z[n], y[2n+1]=Im z[n].
// We keep only y[0..31] (causal half) => store z[n] for n < 16 only.
// ---------------------------------------------------------------------------
__global__ void __launch_bounds__(256) k_stage3(float* __restrict__ out) {
    __shared__ float2 sm[32 * 64];
    const int s   = blockIdx.y;
    const int col = threadIdx.x & 63;
    const int m   = threadIdx.x >> 6;            // 0..3
    const int n2  = blockIdx.x * 64 + col;
    const __half2* gh = g_h + (size_t)s * (33 * N2);

    float2 v[8];
    // Build G[m+4t], t=0..7
    #pragma unroll
    for (int t = 0; t < 8; t++) {
        int k = m + 4*t;                         // 0..31
        float2 Uk = __half22float2(gh[k * N2 + n2]);
        float2 Uc = __half22float2(gh[(32 - k) * N2 + n2]);
        Uc.y = -Uc.y;                            // conj(U[32-k])
        float2 sum  = cadd(Uk, Uc);
        float2 diff = csub(Uk, Uc);
        float2 wk = twidc(32, k);                // e^{+2pi i k/64}
        v[t] = cadd(sum, mulpI(cmul(wk, diff))); // sum + i*w^k*diff
    }
    fft8<true>(v);                               // over t -> n0 (natural order)
    // twiddle W_32^{n0*m}, W_32 = e^{+2pi i/32}
    { float2 W[8];
      twpow(W, twidc(16, m));
      #pragma unroll
      for (int n0 = 1; n0 < 8; n0++) v[n0] = cmul(v[n0], W[n0]);
    }
    #pragma unroll
    for (int n0 = 0; n0 < 8; n0++) sm[(n0*4 + m)*64 + col] = v[n0];
    __syncthreads();

    // fft4<inv> over m for n0 in {2q, 2q+1}; keep z[n] only for n < 16
    const int q = m;                             // 0..3
    float* os = out + (size_t)s * T_LEN;
    #pragma unroll
    for (int h2 = 0; h2 < 2; h2++) {
        const int n0 = 2*q + h2;                 // 0..7
        float2 w4[4];
        #pragma unroll
        for (int mm = 0; mm < 4; mm++) w4[mm] = sm[(n0*4 + mm)*64 + col];
        fft4<true>(w4);                          // over m -> s4 ; n = n0 + 8*s4
        #pragma unroll
        for (int s4 = 0; s4 < 2; s4++) {         // n < 16 => y rows < 32 only
            int n = n0 + 8*s4;                   // 0..15
            os[(2*n)     * N2 + n2] = w4[s4].x;  // y[2n]
            os[(2*n + 1) * N2 + n2] = w4[s4].y;  // y[2n+1]
        }
    }
}

extern "C" void kernel_launch(void* const* d_in, const int* in_sizes, int n_in,
                              void* d_out, int out_size) {
    const float* x = (const float*)d_in[0];
    const float* h = (const float*)d_in[1];
    float* out = (float*)d_out;

    k_init_tw<<<NN / 256, 256>>>();
    k_stage1<<<dim3(N2 / 32, SEQ), 256>>>(x, h);
    k_stage2<<<dim3(32, SEQ), 256>>>();
    k_stage3<<<dim3(N2 / 64, SEQ), 256>>>(out);
}

// round 16
// speedup vs baseline: 1.0005x; 1.0005x over previous
#include <cuda_runtime.h>
#include <cuda_bf16.h>
#include <cuda_fp16.h>

#define SEQ   512
#define T_LEN 65536
#define NN    131072
#define NHALF 65536
#define N2    2048

// Scratch (device globals; no allocations allowed)
__device__ __half2 g_zh[(size_t)SEQ * NN];      // 256 MiB fp16 stage1->2 buffer
__device__ __half2 g_h[(size_t)SEQ * 33 * N2];  // 138 MiB fp16 stage2->3 buffer
__device__ float2 g_tw[NN];                     // g_tw[h+p] = exp(-i*pi*p/h)

static __device__ __forceinline__ float2 cmul(float2 a, float2 b) {
    return make_float2(fmaf(a.x, b.x, -a.y * b.y), fmaf(a.x, b.y, a.y * b.x));
}
static __device__ __forceinline__ float2 cadd(float2 a, float2 b) { return make_float2(a.x+b.x, a.y+b.y); }
static __device__ __forceinline__ float2 csub(float2 a, float2 b) { return make_float2(a.x-b.x, a.y-b.y); }
static __device__ __forceinline__ float2 mulnI(float2 a) { return make_float2(a.y, -a.x); }   // * (-i)
static __device__ __forceinline__ float2 mulpI(float2 a) { return make_float2(-a.y, a.x); }   // * (+i)
static __device__ __forceinline__ float2 cconj(float2 a) { return make_float2(a.x, -a.y); }

// W_{2*Mhalf}^q  for q in [0, 2*Mhalf)
static __device__ __forceinline__ float2 twid(int Mhalf, int q) {
    if (q < Mhalf) return g_tw[Mhalf + q];
    float2 t = g_tw[q];                    // == g_tw[Mhalf + (q - Mhalf)]
    return make_float2(-t.x, -t.y);
}
// conj(W_{2*Mhalf}^q)
static __device__ __forceinline__ float2 twidc(int Mhalf, int q) {
    if (q < Mhalf) { float2 t = g_tw[Mhalf + q]; return make_float2(t.x, -t.y); }
    float2 t = g_tw[q];
    return make_float2(-t.x, t.y);
}

// Powers W[j] = w^j, j=1..7, built with a depth-3 tree (6 cmuls, 1 load).
static __device__ __forceinline__ void twpow(float2 W[8], float2 w) {
    W[1] = w;
    W[2] = cmul(w, w);
    W[3] = cmul(W[2], w);
    W[4] = cmul(W[2], W[2]);
    W[5] = cmul(W[2], W[3]);
    W[6] = cmul(W[3], W[3]);
    W[7] = cmul(W[3], W[4]);
}

// 8-pt DFT, natural in/out. INV => conjugated twiddles (unnormalized inverse).
template<bool INV>
static __device__ __forceinline__ void fft8(float2 z[8]) {
    const float C = 0.70710678118654752440f;
    float2 t0=cadd(z[0],z[4]), t1=cadd(z[1],z[5]), t2=cadd(z[2],z[6]), t3=cadd(z[3],z[7]);
    float2 s0=csub(z[0],z[4]), s1=csub(z[1],z[5]), s2=csub(z[2],z[6]), s3=csub(z[3],z[7]);
    if (!INV) {
        s1 = cmul(s1, make_float2(C,-C)); s2 = mulnI(s2); s3 = cmul(s3, make_float2(-C,-C));
    } else {
        s1 = cmul(s1, make_float2(C, C)); s2 = mulpI(s2); s3 = cmul(s3, make_float2(-C, C));
    }
    float2 a0=cadd(t0,t2), a1=csub(t0,t2), a2=cadd(t1,t3), a3=csub(t1,t3);
    a3 = INV ? mulpI(a3) : mulnI(a3);
    float2 b0=cadd(s0,s2), b1=csub(s0,s2), b2=cadd(s1,s3), b3=csub(s1,s3);
    b3 = INV ? mulpI(b3) : mulnI(b3);
    z[0]=cadd(a0,a2); z[4]=csub(a0,a2);
    z[2]=cadd(a1,a3); z[6]=csub(a1,a3);
    z[1]=cadd(b0,b2); z[5]=csub(b0,b2);
    z[3]=cadd(b1,b3); z[7]=csub(b1,b3);
}

template<bool INV>
static __device__ __forceinline__ void fft4(float2 z[4]) {
    float2 a0=cadd(z[0],z[2]), a1=csub(z[0],z[2]);
    float2 a2=cadd(z[1],z[3]), a3=csub(z[1],z[3]);
    a3 = INV ? mulpI(a3) : mulnI(a3);
    z[0]=cadd(a0,a2); z[2]=csub(a0,a2);
    z[1]=cadd(a1,a3); z[3]=csub(a1,a3);
}

// 16-pt DFT, natural in/out, via 4x4 Cooley-Tukey. INV => conj twiddles.
template<bool INV>
static __device__ __forceinline__ void fft16(float2 z[16]) {
    const float C1 = 0.92387953251128675613f;   // cos(pi/8)
    const float S1 = 0.38268343236508977173f;   // sin(pi/8)
    const float R  = 0.70710678118654752440f;
    const float2 W1 = INV ? make_float2(C1,  S1) : make_float2(C1, -S1);
    const float2 W2 = INV ? make_float2(R,   R ) : make_float2(R,  -R );
    const float2 W3 = INV ? make_float2(S1,  C1) : make_float2(S1, -C1);
    const float2 W6 = INV ? make_float2(-R,  R ) : make_float2(-R, -R );
    const float2 W9 = INV ? make_float2(-C1,-S1) : make_float2(-C1, S1);
    float2 t[16];
    #pragma unroll
    for (int b = 0; b < 4; b++) {
        float2 q[4] = { z[b], z[4+b], z[8+b], z[12+b] };
        fft4<INV>(q);
        if (b == 1) { q[1]=cmul(q[1],W1); q[2]=cmul(q[2],W2); q[3]=cmul(q[3],W3); }
        if (b == 2) { q[1]=cmul(q[1],W2); q[2]= INV?mulpI(q[2]):mulnI(q[2]); q[3]=cmul(q[3],W6); }
        if (b == 3) { q[1]=cmul(q[1],W3); q[2]=cmul(q[2],W6); q[3]=cmul(q[3],W9); }
        t[b] = q[0]; t[4+b] = q[1]; t[8+b] = q[2]; t[12+b] = q[3];
    }
    #pragma unroll
    for (int c = 0; c < 4; c++) {
        float2 q[4] = { t[4*c+0], t[4*c+1], t[4*c+2], t[4*c+3] };
        fft4<INV>(q);
        z[c] = q[0]; z[c+4] = q[1]; z[c+8] = q[2]; z[c+12] = q[3];
    }
}

// Hermitian unpack + pointwise: Za = Z[k], Zb = Z[N-k]; returns Y[k] = X[k]*H[k]
static __device__ __forceinline__ float2 pw(float2 Za, float2 Zb) {
    float2 X = make_float2(0.5f*(Za.x+Zb.x),  0.5f*(Za.y-Zb.y));
    float2 H = make_float2(0.5f*(Za.y+Zb.y), -0.5f*(Za.x-Zb.x));
    return cmul(X, H);
}

#define PAD(p) ((p) + (((p) >> 5) << 2))
// digit-reversed position for plan 16(str128),16(str8),8(str1):
// k2 = j + 16*j2 + 256*j3  ->  p = 128*j + 8*j2 + j3
#define POS16(k2) ((((k2) & 15) << 7) + ((((k2) >> 4) & 15) << 3) + ((k2) >> 8))

__global__ void k_init_tw() {
    int idx = blockIdx.x * blockDim.x + threadIdx.x;
    if (idx >= NN) return;
    if (idx == 0) { g_tw[0] = make_float2(1.0f, 0.0f); return; }
    int h = 1 << (31 - __clz(idx));
    int p = idx - h;
    float s, c;
    sincospif(-(float)p / (float)h, &s, &c);
    g_tw[idx] = make_float2(c, s);
}

// ---------------------------------------------------------------------------
// Stage 1: pack z = bf16(x) + i*h (rows n1>=32 are zero) + 64-pt FFT along n1
// (two register radix-8 passes, one smem exchange) + twiddle W_N^{k1*n2}.
// Output (fp16): g_zh[s][k1*2048 + n2]
// ---------------------------------------------------------------------------
__global__ void __launch_bounds__(256) k_stage1(const float* __restrict__ x,
                                                const float* __restrict__ hk) {
    __shared__ float2 sm[64 * 32];
    const int s   = blockIdx.y;
    const int col = threadIdx.x & 31;
    const int a   = threadIdx.x >> 5;          // 0..7
    const int n2  = blockIdx.x * 32 + col;
    const float* xs = x  + (size_t)s * T_LEN;
    const float* hs = hk + (size_t)s * T_LEN;

    float2 v[8];
    #pragma unroll
    for (int b = 0; b < 4; b++) {
        int n = (a + 8*b) * N2 + n2;           // < 65536 always
        v[b] = make_float2(__bfloat162float(__float2bfloat16_rn(xs[n])), hs[n]);
    }
    // fft8 over b with upper half zero (t = z, s = z)
    {
        const float C = 0.70710678118654752440f;
        float2 t0=v[0], t1=v[1], t2=v[2], t3=v[3];
        float2 s0=v[0];
        float2 s1=cmul(v[1], make_float2(C,-C));
        float2 s2=mulnI(v[2]);
        float2 s3=cmul(v[3], make_float2(-C,-C));
        float2 a0=cadd(t0,t2), a1=csub(t0,t2), a2=cadd(t1,t3), a3=mulnI(csub(t1,t3));
        float2 b0=cadd(s0,s2), b1=csub(s0,s2), b2=cadd(s1,s3), b3=mulnI(csub(s1,s3));
        v[0]=cadd(a0,a2); v[4]=csub(a0,a2);
        v[2]=cadd(a1,a3); v[6]=csub(a1,a3);
        v[1]=cadd(b0,b2); v[5]=csub(b0,b2);
        v[3]=cadd(b1,b3); v[7]=csub(b1,b3);
    }
    // twiddle W_64^{a*j}
    {
        float2 W[8];
        twpow(W, twid(32, a));
        #pragma unroll
        for (int j = 1; j < 8; j++) v[j] = cmul(v[j], W[j]);
    }
    #pragma unroll
    for (int j = 0; j < 8; j++) sm[(j*8 + a)*32 + col] = v[j];
    __syncthreads();

    const int j = a;                            // phase-2 role
    #pragma unroll
    for (int q = 0; q < 8; q++) v[q] = sm[(j*8 + q)*32 + col];
    fft8<false>(v);                             // over a -> m ; k1 = j + 8m

    __half2* zs = g_zh + (size_t)s * NN;
    {
        float2 acc  = twid(NHALF, n2 * j);      // n2*j < 65536
        float2 step = twid(NHALF, 8 * n2);
        #pragma unroll
        for (int m = 0; m < 8; m++) {
            int k1 = j + 8*m;
            float2 y = cmul(v[m], acc);
            zs[k1 * N2 + n2] = __floats2half2_rn(y.x, y.y);
            acc = cmul(acc, step);
        }
    }
}

// ---------------------------------------------------------------------------
// Stage 2 (radix-16 plan 2048 = 16x16x8, 256 threads, 3 blocks/SM):
// pair {g, 64-g} ({0,32} for g==0). Twiddle loops use 4 interleaved chains
// (depth ~5 instead of 15) to keep the 16 smem ops per loop pipelined.
// ---------------------------------------------------------------------------
__global__ void __launch_bounds__(256, 3) k_stage2() {
    __shared__ float2 smA[2304];
    __shared__ float2 smB[2304];
    const int s = blockIdx.y;
    const int g = blockIdx.x;                   // 0..31
    const int rowA = g;
    const int rowB = (g == 0) ? 32 : 64 - g;
    const int u = threadIdx.x;                  // 0..255
    const __half2* zb = g_zh + (size_t)s * NN;

    float2 v[16];

    // ---- S1: radix-16 over stride 128, twiddle W_2048^{c*j} ----
    {
        const int r = u >> 7, c = u & 127;
        const __half2* glob = zb + (r ? rowB : rowA) * N2;
        float2* sm = r ? smB : smA;
        #pragma unroll
        for (int t = 0; t < 16; t++) v[t] = __half22float2(glob[c + 128*t]);
        fft16<false>(v);
        float2 w1 = twid(1024, c);
        float2 w2 = cmul(w1, w1), w3 = cmul(w2, w1), w4 = cmul(w2, w2);
        sm[PAD(c)]          = v[0];
        sm[PAD(128*1 + c)]  = cmul(v[1], w1);
        sm[PAD(128*2 + c)]  = cmul(v[2], w2);
        sm[PAD(128*3 + c)]  = cmul(v[3], w3);
        float2 a0 = w4, a1 = cmul(w1, w4), a2 = cmul(w2, w4), a3 = cmul(w3, w4);
        #pragma unroll
        for (int rr4 = 1; rr4 < 4; rr4++) {
            sm[PAD(128*(4*rr4+0) + c)] = cmul(v[4*rr4+0], a0);
            sm[PAD(128*(4*rr4+1) + c)] = cmul(v[4*rr4+1], a1);
            sm[PAD(128*(4*rr4+2) + c)] = cmul(v[4*rr4+2], a2);
            sm[PAD(128*(4*rr4+3) + c)] = cmul(v[4*rr4+3], a3);
            if (rr4 < 3) { a0=cmul(a0,w4); a1=cmul(a1,w4); a2=cmul(a2,w4); a3=cmul(a3,w4); }
        }
    }
    __syncthreads();

    // ---- S2: radix-16 over stride 8, twiddle W_128^{e*j2} ----
    {
        const int r = u >> 7, idx = u & 127, j = idx >> 3, e = idx & 7;
        float2* sm = r ? smB : smA;
        const int base = 128*j + e;
        #pragma unroll
        for (int t2 = 0; t2 < 16; t2++) v[t2] = sm[PAD(base + 8*t2)];
        fft16<false>(v);
        float2 w1 = twid(64, e);
        float2 w2 = cmul(w1, w1), w3 = cmul(w2, w1), w4 = cmul(w2, w2);
        sm[PAD(base)]          = v[0];
        sm[PAD(base + 8*1)]    = cmul(v[1], w1);
        sm[PAD(base + 8*2)]    = cmul(v[2], w2);
        sm[PAD(base + 8*3)]    = cmul(v[3], w3);
        float2 a0 = w4, a1 = cmul(w1, w4), a2 = cmul(w2, w4), a3 = cmul(w3, w4);
        #pragma unroll
        for (int rr4 = 1; rr4 < 4; rr4++) {
            sm[PAD(base + 8*(4*rr4+0))] = cmul(v[4*rr4+0], a0);
            sm[PAD(base + 8*(4*rr4+1))] = cmul(v[4*rr4+1], a1);
            sm[PAD(base + 8*(4*rr4+2))] = cmul(v[4*rr4+2], a2);
            sm[PAD(base + 8*(4*rr4+3))] = cmul(v[4*rr4+3], a3);
            if (rr4 < 3) { a0=cmul(a0,w4); a1=cmul(a1,w4); a2=cmul(a2,w4); a3=cmul(a3,w4); }
        }
    }
    __syncthreads();

    if (g != 0) {
        // FUSED S3 fwd (A and B) + pointwise + IS3, all in registers.
        // A position p = 8u + j3 pairs with B position 2047-p = 8(255-u)+(7-j3).
        float2 a8[8], b8[8];
        #pragma unroll
        for (int e = 0; e < 8; e++) {
            a8[e] = smA[PAD(8*u + e)];
            b8[e] = smB[PAD(8*(255 - u) + e)];
        }
        fft8<false>(a8);
        fft8<false>(b8);
        float2 ya[8];
        #pragma unroll
        for (int j3 = 0; j3 < 8; j3++) ya[j3] = pw(a8[j3], b8[7 - j3]);
        fft8<true>(ya);
        #pragma unroll
        for (int e = 0; e < 8; e++) smA[PAD(8*u + e)] = ya[e];
    } else {
        // g==0: S3 forward both rows (in place per thread block-of-8)
        #pragma unroll
        for (int r = 0; r < 2; r++) {
            float2* sm = r ? smB : smA;
            float2 s8[8];
            #pragma unroll
            for (int e = 0; e < 8; e++) s8[e] = sm[PAD(8*u + e)];
            fft8<false>(s8);
            #pragma unroll
            for (int j3 = 0; j3 < 8; j3++) sm[PAD(8*u + j3)] = s8[j3];
        }
        __syncthreads();
        // row 0: pairs k2 <-> (2048-k2) mod 2048 (explicit POS16)
        #pragma unroll
        for (int e = 0; e < 4; e++) {
            int k2 = 4*u + e;                    // 0..1023
            int pa = POS16(k2);
            int pb = POS16((2048 - k2) & 2047);
            float2 Za = smA[PAD(pa)];
            float2 Zb = smA[PAD(pb)];
            float2 Y = pw(Za, Zb);
            smA[PAD(pa)] = Y;
            smA[PAD(pb)] = cconj(Y);
        }
        if (u == 0) {                            // k2 = 1024 self-pair
            int pa = POS16(1024);
            float2 Za = smA[PAD(pa)];
            smA[PAD(pa)] = pw(Za, Za);
        }
        // row 32: position-local p <-> 2047-p
        #pragma unroll
        for (int e = 0; e < 4; e++) {
            int p = 4*u + e;                     // 0..1023
            float2 Za = smB[PAD(p)];
            float2 Zb = smB[PAD(2047 - p)];
            float2 Y = pw(Za, Zb);
            smB[PAD(p)]        = Y;
            smB[PAD(2047 - p)] = cconj(Y);
        }
        __syncthreads();
        // IS3 both rows
        #pragma unroll
        for (int r = 0; r < 2; r++) {
            float2* sm = r ? smB : smA;
            float2 s8[8];
            #pragma unroll
            for (int j3 = 0; j3 < 8; j3++) s8[j3] = sm[PAD(8*u + j3)];
            fft8<true>(s8);
            #pragma unroll
            for (int e = 0; e < 8; e++) sm[PAD(8*u + e)] = s8[e];
        }
    }
    __syncthreads();

    const int rI = u >> 7, idxI = u & 127;
    const bool act = (rI == 0) || (g == 0);
    float2* smI = rI ? smB : smA;
    const int rowI = rI ? rowB : rowA;

    // ---- IS2: conj twiddle W_128^{-e*j2} (input side), inverse radix-16 ----
    // In-place safe: writes have low3 bits == e, only read by the same thread.
    if (act) {
        const int j = idxI >> 3, e = idxI & 7;
        const int base = 128*j + e;
        float2 w1 = twidc(64, e);
        float2 w2 = cmul(w1, w1), w3 = cmul(w2, w1), w4 = cmul(w2, w2);
        v[0] = smI[PAD(base)];
        v[1] = cmul(smI[PAD(base + 8*1)], w1);
        v[2] = cmul(smI[PAD(base + 8*2)], w2);
        v[3] = cmul(smI[PAD(base + 8*3)], w3);
        float2 a0 = w4, a1 = cmul(w1, w4), a2 = cmul(w2, w4), a3 = cmul(w3, w4);
        #pragma unroll
        for (int rr4 = 1; rr4 < 4; rr4++) {
            v[4*rr4+0] = cmul(smI[PAD(base + 8*(4*rr4+0))], a0);
            v[4*rr4+1] = cmul(smI[PAD(base + 8*(4*rr4+1))], a1);
            v[4*rr4+2] = cmul(smI[PAD(base + 8*(4*rr4+2))], a2);
            v[4*rr4+3] = cmul(smI[PAD(base + 8*(4*rr4+3))], a3);
            if (rr4 < 3) { a0=cmul(a0,w4); a1=cmul(a1,w4); a2=cmul(a2,w4); a3=cmul(a3,w4); }
        }
        fft16<true>(v);
        #pragma unroll
        for (int t2 = 0; t2 < 16; t2++) smI[PAD(base + 8*t2)] = v[t2];
    }
    __syncthreads();

    // ---- IS1: conj twiddle W_2048^{-c*j}, inverse radix-16, inter-twiddle
    //      W_N^{-row*(c+128t)} with 1/N folded, store fp16 ----
    if (act) {
        const int c = idxI;
        float2 w1 = twidc(1024, c);
        float2 w2 = cmul(w1, w1), w3 = cmul(w2, w1), w4 = cmul(w2, w2);
        v[0] = smI[PAD(c)];
        v[1] = cmul(smI[PAD(128*1 + c)], w1);
        v[2] = cmul(smI[PAD(128*2 + c)], w2);
        v[3] = cmul(smI[PAD(128*3 + c)], w3);
        float2 a0 = w4, a1 = cmul(w1, w4), a2 = cmul(w2, w4), a3 = cmul(w3, w4);
        #pragma unroll
        for (int rr4 = 1; rr4 < 4; rr4++) {
            v[4*rr4+0] = cmul(smI[PAD(128*(4*rr4+0) + c)], a0);
            v[4*rr4+1] = cmul(smI[PAD(128*(4*rr4+1) + c)], a1);
            v[4*rr4+2] = cmul(smI[PAD(128*(4*rr4+2) + c)], a2);
            v[4*rr4+3] = cmul(smI[PAD(128*(4*rr4+3) + c)], a3);
            if (rr4 < 3) { a0=cmul(a0,w4); a1=cmul(a1,w4); a2=cmul(a2,w4); a3=cmul(a3,w4); }
        }
        fft16<true>(v);
        const float SC = 1.0f / (float)NN;
        float2 b0 = twidc(NHALF, rowI * c);      // rowI*c <= 32*127 < 65536
        b0.x *= SC; b0.y *= SC;
        float2 st  = twidc(NHALF, 128 * rowI);   // <= 4096
        float2 st2 = cmul(st, st), st4 = cmul(st2, st2);
        float2 b1 = cmul(b0, st), b2 = cmul(b0, st2), b3 = cmul(b1, st2);
        __half2* gh = g_h + (size_t)s * (33 * N2) + rowI * N2;
        #pragma unroll
        for (int rr4 = 0; rr4 < 4; rr4++) {
            float2 y0 = cmul(v[4*rr4+0], b0);
            float2 y1 = cmul(v[4*rr4+1], b1);
            float2 y2 = cmul(v[4*rr4+2], b2);
            float2 y3 = cmul(v[4*rr4+3], b3);
            gh[c + 128*(4*rr4+0)] = __floats2half2_rn(y0.x, y0.y);
            gh[c + 128*(4*rr4+1)] = __floats2half2_rn(y1.x, y1.y);
            gh[c + 128*(4*rr4+2)] = __floats2half2_rn(y2.x, y2.y);
            gh[c + 128*(4*rr4+3)] = __floats2half2_rn(y3.x, y3.y);
            if (rr4 < 3) { b0=cmul(b0,st4); b1=cmul(b1,st4); b2=cmul(b2,st4); b3=cmul(b3,st4); }
        }
    }
}

// ---------------------------------------------------------------------------
// Stage 3 (real-output half-size IFFT): per column n2, build
//   G[k] = (U[k] + conj(U[32-k])) + i*w^k*(U[k] - conj(U[32-k])), w=e^{2pi i/64}
// from U rows 0..32 (fp16), then z = IFFT_32(G): y[2n]=Re z[n], y[2n+1]=Im z[n].
// We keep only y[0..31] (causal half) => store z[n] for n < 16 only.
// ---------------------------------------------------------------------------
__global__ void __launch_bounds__(256) k_stage3(float* __restrict__ out) {
    __shared__ float2 sm[32 * 64];
    const int s   = blockIdx.y;
    const int col = threadIdx.x & 63;
    const int m   = threadIdx.x >> 6;            // 0..3
    const int n2  = blockIdx.x * 64 + col;
    const __half2* gh = g_h + (size_t)s * (33 * N2);

    float2 v[8];
    // Build G[m+4t], t=0..7
    #pragma unroll
    for (int t = 0; t < 8; t++) {
        int k = m + 4*t;                         // 0..31
        float2 Uk = __half22float2(gh[k * N2 + n2]);
        float2 Uc = __half22float2(gh[(32 - k) * N2 + n2]);
        Uc.y = -Uc.y;                            // conj(U[32-k])
        float2 sum  = cadd(Uk, Uc);
        float2 diff = csub(Uk, Uc);
        float2 wk = twidc(32, k);                // e^{+2pi i k/64}
        v[t] = cadd(sum, mulpI(cmul(wk, diff))); // sum + i*w^k*diff
    }
    fft8<true>(v);                               // over t -> n0 (natural order)
    // twiddle W_32^{n0*m}, W_32 = e^{+2pi i/32}
    { float2 W[8];
      twpow(W, twidc(16, m));
      #pragma unroll
      for (int n0 = 1; n0 < 8; n0++) v[n0] = cmul(v[n0], W[n0]);
    }
    #pragma unroll
    for (int n0 = 0; n0 < 8; n0++) sm[(n0*4 + m)*64 + col] = v[n0];
    __syncthreads();

    // fft4<inv> over m for n0 in {2q, 2q+1}; keep z[n] only for n < 16
    const int q = m;                             // 0..3
    float* os = out + (size_t)s * T_LEN;
    #pragma unroll
    for (int h2 = 0; h2 < 2; h2++) {
        const int n0 = 2*q + h2;                 // 0..7
        float2 w4[4];
        #pragma unroll
        for (int mm = 0; mm < 4; mm++) w4[mm] = sm[(n0*4 + mm)*64 + col];
        fft4<true>(w4);                          // over m -> s4 ; n = n0 + 8*s4
        #pragma unroll
        for (int s4 = 0; s4 < 2; s4++) {         // n < 16 => y rows < 32 only
            int n = n0 + 8*s4;                   // 0..15
            os[(2*n)     * N2 + n2] = w4[s4].x;  // y[2n]
            os[(2*n + 1) * N2 + n2] = w4[s4].y;  // y[2n+1]
        }
    }
}

extern "C" void kernel_launch(void* const* d_in, const int* in_sizes, int n_in,
                              void* d_out, int out_size) {
    const float* x = (const float*)d_in[0];
    const float* h = (const float*)d_in[1];
    float* out = (float*)d_out;

    k_init_tw<<<NN / 256, 256>>>();
    k_stage1<<<dim3(N2 / 32, SEQ), 256>>>(x, h);
    k_stage2<<<dim3(32, SEQ), 256>>>();
    k_stage3<<<dim3(N2 / 64, SEQ), 256>>>(out);
}

// round 17
// speedup vs baseline: 1.0556x; 1.0550x over previous
#include <cuda_runtime.h>
#include <cuda_bf16.h>
#include <cuda_fp16.h>

#define SEQ   512
#define T_LEN 65536
#define NN    131072
#define NHALF 65536
#define N2    2048

// Scratch (device globals; no allocations allowed)
__device__ __half2 g_zh[(size_t)SEQ * NN];      // 256 MiB fp16 stage1->2 buffer
__device__ __half2 g_h[(size_t)SEQ * 33 * N2];  // 138 MiB fp16 stage2->3 buffer
__device__ float2 g_tw[NN];                     // g_tw[h+p] = exp(-i*pi*p/h)

static __device__ __forceinline__ float2 cmul(float2 a, float2 b) {
    return make_float2(fmaf(a.x, b.x, -a.y * b.y), fmaf(a.x, b.y, a.y * b.x));
}
// Packed complex add/sub: ONE add.rn.f32x2 instead of two FADDs (ptxas never
// auto-fuses; PTX-only). Rounding identical to scalar fp32 adds.
static __device__ __forceinline__ float2 cadd(float2 a, float2 b) {
    float2 r;
    asm("{\n\t"
        ".reg .b64 ra, rb, rc;\n\t"
        "mov.b64 ra, {%2, %3};\n\t"
        "mov.b64 rb, {%4, %5};\n\t"
        "add.rn.f32x2 rc, ra, rb;\n\t"
        "mov.b64 {%0, %1}, rc;\n\t"
        "}"
        : "=f"(r.x), "=f"(r.y)
        : "f"(a.x), "f"(a.y), "f"(b.x), "f"(b.y));
    return r;
}
static __device__ __forceinline__ float2 csub(float2 a, float2 b) {
    float2 r;
    asm("{\n\t"
        ".reg .b64 ra, rb, rc;\n\t"
        "mov.b64 ra, {%2, %3};\n\t"
        "neg.f32 %0, %4;\n\t"
        "neg.f32 %1, %5;\n\t"
        "mov.b64 rb, {%0, %1};\n\t"
        "add.rn.f32x2 rc, ra, rb;\n\t"
        "mov.b64 {%0, %1}, rc;\n\t"
        "}"
        : "=f"(r.x), "=f"(r.y)
        : "f"(a.x), "f"(a.y), "f"(b.x), "f"(b.y));
    return r;
}
static __device__ __forceinline__ float2 mulnI(float2 a) { return make_float2(a.y, -a.x); }   // * (-i)
static __device__ __forceinline__ float2 mulpI(float2 a) { return make_float2(-a.y, a.x); }   // * (+i)
static __device__ __forceinline__ float2 cconj(float2 a) { return make_float2(a.x, -a.y); }

// W_{2*Mhalf}^q  for q in [0, 2*Mhalf)
static __device__ __forceinline__ float2 twid(int Mhalf, int q) {
    if (q < Mhalf) return g_tw[Mhalf + q];
    float2 t = g_tw[q];                    // == g_tw[Mhalf + (q - Mhalf)]
    return make_float2(-t.x, -t.y);
}
// conj(W_{2*Mhalf}^q)
static __device__ __forceinline__ float2 twidc(int Mhalf, int q) {
    if (q < Mhalf) { float2 t = g_tw[Mhalf + q]; return make_float2(t.x, -t.y); }
    float2 t = g_tw[q];
    return make_float2(-t.x, t.y);
}

// Powers W[j] = w^j, j=1..7, built with a depth-3 tree (6 cmuls, 1 load).
static __device__ __forceinline__ void twpow(float2 W[8], float2 w) {
    W[1] = w;
    W[2] = cmul(w, w);
    W[3] = cmul(W[2], w);
    W[4] = cmul(W[2], W[2]);
    W[5] = cmul(W[2], W[3]);
    W[6] = cmul(W[3], W[3]);
    W[7] = cmul(W[3], W[4]);
}

// 8-pt DFT, natural in/out. INV => conjugated twiddles (unnormalized inverse).
template<bool INV>
static __device__ __forceinline__ void fft8(float2 z[8]) {
    const float C = 0.70710678118654752440f;
    float2 t0=cadd(z[0],z[4]), t1=cadd(z[1],z[5]), t2=cadd(z[2],z[6]), t3=cadd(z[3],z[7]);
    float2 s0=csub(z[0],z[4]), s1=csub(z[1],z[5]), s2=csub(z[2],z[6]), s3=csub(z[3],z[7]);
    if (!INV) {
        s1 = cmul(s1, make_float2(C,-C)); s2 = mulnI(s2); s3 = cmul(s3, make_float2(-C,-C));
    } else {
        s1 = cmul(s1, make_float2(C, C)); s2 = mulpI(s2); s3 = cmul(s3, make_float2(-C, C));
    }
    float2 a0=cadd(t0,t2), a1=csub(t0,t2), a2=cadd(t1,t3), a3=csub(t1,t3);
    a3 = INV ? mulpI(a3) : mulnI(a3);
    float2 b0=cadd(s0,s2), b1=csub(s0,s2), b2=cadd(s1,s3), b3=csub(s1,s3);
    b3 = INV ? mulpI(b3) : mulnI(b3);
    z[0]=cadd(a0,a2); z[4]=csub(a0,a2);
    z[2]=cadd(a1,a3); z[6]=csub(a1,a3);
    z[1]=cadd(b0,b2); z[5]=csub(b0,b2);
    z[3]=cadd(b1,b3); z[7]=csub(b1,b3);
}

template<bool INV>
static __device__ __forceinline__ void fft4(float2 z[4]) {
    float2 a0=cadd(z[0],z[2]), a1=csub(z[0],z[2]);
    float2 a2=cadd(z[1],z[3]), a3=csub(z[1],z[3]);
    a3 = INV ? mulpI(a3) : mulnI(a3);
    z[0]=cadd(a0,a2); z[2]=csub(a0,a2);
    z[1]=cadd(a1,a3); z[3]=csub(a1,a3);
}

// 16-pt DFT, natural in/out, via 4x4 Cooley-Tukey. INV => conj twiddles.
template<bool INV>
static __device__ __forceinline__ void fft16(float2 z[16]) {
    const float C1 = 0.92387953251128675613f;   // cos(pi/8)
    const float S1 = 0.38268343236508977173f;   // sin(pi/8)
    const float R  = 0.70710678118654752440f;
    const float2 W1 = INV ? make_float2(C1,  S1) : make_float2(C1, -S1);
    const float2 W2 = INV ? make_float2(R,   R ) : make_float2(R,  -R );
    const float2 W3 = INV ? make_float2(S1,  C1) : make_float2(S1, -C1);
    const float2 W6 = INV ? make_float2(-R,  R ) : make_float2(-R, -R );
    const float2 W9 = INV ? make_float2(-C1,-S1) : make_float2(-C1, S1);
    float2 t[16];
    #pragma unroll
    for (int b = 0; b < 4; b++) {
        float2 q[4] = { z[b], z[4+b], z[8+b], z[12+b] };
        fft4<INV>(q);
        if (b == 1) { q[1]=cmul(q[1],W1); q[2]=cmul(q[2],W2); q[3]=cmul(q[3],W3); }
        if (b == 2) { q[1]=cmul(q[1],W2); q[2]= INV?mulpI(q[2]):mulnI(q[2]); q[3]=cmul(q[3],W6); }
        if (b == 3) { q[1]=cmul(q[1],W3); q[2]=cmul(q[2],W6); q[3]=cmul(q[3],W9); }
        t[b] = q[0]; t[4+b] = q[1]; t[8+b] = q[2]; t[12+b] = q[3];
    }
    #pragma unroll
    for (int c = 0; c < 4; c++) {
        float2 q[4] = { t[4*c+0], t[4*c+1], t[4*c+2], t[4*c+3] };
        fft4<INV>(q);
        z[c] = q[0]; z[c+4] = q[1]; z[c+8] = q[2]; z[c+12] = q[3];
    }
}

// Hermitian unpack + pointwise: Za = Z[k], Zb = Z[N-k]; returns Y[k] = X[k]*H[k]
static __device__ __forceinline__ float2 pw(float2 Za, float2 Zb) {
    float2 X = make_float2(0.5f*(Za.x+Zb.x),  0.5f*(Za.y-Zb.y));
    float2 H = make_float2(0.5f*(Za.y+Zb.y), -0.5f*(Za.x-Zb.x));
    return cmul(X, H);
}

#define PAD(p) ((p) + (((p) >> 5) << 2))
// digit-reversed position for plan 16(str128),16(str8),8(str1):
// k2 = j + 16*j2 + 256*j3  ->  p = 128*j + 8*j2 + j3
#define POS16(k2) ((((k2) & 15) << 7) + ((((k2) >> 4) & 15) << 3) + ((k2) >> 8))

__global__ void k_init_tw() {
    int idx = blockIdx.x * blockDim.x + threadIdx.x;
    if (idx >= NN) return;
    if (idx == 0) { g_tw[0] = make_float2(1.0f, 0.0f); return; }
    int h = 1 << (31 - __clz(idx));
    int p = idx - h;
    float s, c;
    sincospif(-(float)p / (float)h, &s, &c);
    g_tw[idx] = make_float2(c, s);
}

// ---------------------------------------------------------------------------
// Stage 1: pack z = bf16(x) + i*h (rows n1>=32 are zero) + 64-pt FFT along n1
// (two register radix-8 passes, one smem exchange) + twiddle W_N^{k1*n2}.
// Output (fp16): g_zh[s][k1*2048 + n2]
// ---------------------------------------------------------------------------
__global__ void __launch_bounds__(256) k_stage1(const float* __restrict__ x,
                                                const float* __restrict__ hk) {
    __shared__ float2 sm[64 * 32];
    const int s   = blockIdx.y;
    const int col = threadIdx.x & 31;
    const int a   = threadIdx.x >> 5;          // 0..7
    const int n2  = blockIdx.x * 32 + col;
    const float* xs = x  + (size_t)s * T_LEN;
    const float* hs = hk + (size_t)s * T_LEN;

    float2 v[8];
    #pragma unroll
    for (int b = 0; b < 4; b++) {
        int n = (a + 8*b) * N2 + n2;           // < 65536 always
        v[b] = make_float2(__bfloat162float(__float2bfloat16_rn(xs[n])), hs[n]);
    }
    // fft8 over b with upper half zero (t = z, s = z)
    {
        const float C = 0.70710678118654752440f;
        float2 t0=v[0], t1=v[1], t2=v[2], t3=v[3];
        float2 s0=v[0];
        float2 s1=cmul(v[1], make_float2(C,-C));
        float2 s2=mulnI(v[2]);
        float2 s3=cmul(v[3], make_float2(-C,-C));
        float2 a0=cadd(t0,t2), a1=csub(t0,t2), a2=cadd(t1,t3), a3=mulnI(csub(t1,t3));
        float2 b0=cadd(s0,s2), b1=csub(s0,s2), b2=cadd(s1,s3), b3=mulnI(csub(s1,s3));
        v[0]=cadd(a0,a2); v[4]=csub(a0,a2);
        v[2]=cadd(a1,a3); v[6]=csub(a1,a3);
        v[1]=cadd(b0,b2); v[5]=csub(b0,b2);
        v[3]=cadd(b1,b3); v[7]=csub(b1,b3);
    }
    // twiddle W_64^{a*j}
    {
        float2 W[8];
        twpow(W, twid(32, a));
        #pragma unroll
        for (int j = 1; j < 8; j++) v[j] = cmul(v[j], W[j]);
    }
    #pragma unroll
    for (int j = 0; j < 8; j++) sm[(j*8 + a)*32 + col] = v[j];
    __syncthreads();

    const int j = a;                            // phase-2 role
    #pragma unroll
    for (int q = 0; q < 8; q++) v[q] = sm[(j*8 + q)*32 + col];
    fft8<false>(v);                             // over a -> m ; k1 = j + 8m

    __half2* zs = g_zh + (size_t)s * NN;
    {
        float2 acc  = twid(NHALF, n2 * j);      // n2*j < 65536
        float2 step = twid(NHALF, 8 * n2);
        #pragma unroll
        for (int m = 0; m < 8; m++) {
            int k1 = j + 8*m;
            float2 y = cmul(v[m], acc);
            zs[k1 * N2 + n2] = __floats2half2_rn(y.x, y.y);
            acc = cmul(acc, step);
        }
    }
}

// ---------------------------------------------------------------------------
// Stage 2 (radix-16 plan 2048 = 16x16x8, 256 threads, 3 blocks/SM):
// pair {g, 64-g} ({0,32} for g==0). Twiddle loops use 4 interleaved chains.
// ---------------------------------------------------------------------------
__global__ void __launch_bounds__(256, 3) k_stage2() {
    __shared__ float2 smA[2304];
    __shared__ float2 smB[2304];
    const int s = blockIdx.y;
    const int g = blockIdx.x;                   // 0..31
    const int rowA = g;
    const int rowB = (g == 0) ? 32 : 64 - g;
    const int u = threadIdx.x;                  // 0..255
    const __half2* zb = g_zh + (size_t)s * NN;

    float2 v[16];

    // ---- S1: radix-16 over stride 128, twiddle W_2048^{c*j} ----
    {
        const int r = u >> 7, c = u & 127;
        const __half2* glob = zb + (r ? rowB : rowA) * N2;
        float2* sm = r ? smB : smA;
        #pragma unroll
        for (int t = 0; t < 16; t++) v[t] = __half22float2(glob[c + 128*t]);
        fft16<false>(v);
        float2 w1 = twid(1024, c);
        float2 w2 = cmul(w1, w1), w3 = cmul(w2, w1), w4 = cmul(w2, w2);
        sm[PAD(c)]          = v[0];
        sm[PAD(128*1 + c)]  = cmul(v[1], w1);
        sm[PAD(128*2 + c)]  = cmul(v[2], w2);
        sm[PAD(128*3 + c)]  = cmul(v[3], w3);
        float2 a0 = w4, a1 = cmul(w1, w4), a2 = cmul(w2, w4), a3 = cmul(w3, w4);
        #pragma unroll
        for (int rr4 = 1; rr4 < 4; rr4++) {
            sm[PAD(128*(4*rr4+0) + c)] = cmul(v[4*rr4+0], a0);
            sm[PAD(128*(4*rr4+1) + c)] = cmul(v[4*rr4+1], a1);
            sm[PAD(128*(4*rr4+2) + c)] = cmul(v[4*rr4+2], a2);
            sm[PAD(128*(4*rr4+3) + c)] = cmul(v[4*rr4+3], a3);
            if (rr4 < 3) { a0=cmul(a0,w4); a1=cmul(a1,w4); a2=cmul(a2,w4); a3=cmul(a3,w4); }
        }
    }
    __syncthreads();

    // ---- S2: radix-16 over stride 8, twiddle W_128^{e*j2} ----
    {
        const int r = u >> 7, idx = u & 127, j = idx >> 3, e = idx & 7;
        float2* sm = r ? smB : smA;
        const int base = 128*j + e;
        #pragma unroll
        for (int t2 = 0; t2 < 16; t2++) v[t2] = sm[PAD(base + 8*t2)];
        fft16<false>(v);
        float2 w1 = twid(64, e);
        float2 w2 = cmul(w1, w1), w3 = cmul(w2, w1), w4 = cmul(w2, w2);
        sm[PAD(base)]          = v[0];
        sm[PAD(base + 8*1)]    = cmul(v[1], w1);
        sm[PAD(base + 8*2)]    = cmul(v[2], w2);
        sm[PAD(base + 8*3)]    = cmul(v[3], w3);
        float2 a0 = w4, a1 = cmul(w1, w4), a2 = cmul(w2, w4), a3 = cmul(w3, w4);
        #pragma unroll
        for (int rr4 = 1; rr4 < 4; rr4++) {
            sm[PAD(base + 8*(4*rr4+0))] = cmul(v[4*rr4+0], a0);
            sm[PAD(base + 8*(4*rr4+1))] = cmul(v[4*rr4+1], a1);
            sm[PAD(base + 8*(4*rr4+2))] = cmul(v[4*rr4+2], a2);
            sm[PAD(base + 8*(4*rr4+3))] = cmul(v[4*rr4+3], a3);
            if (rr4 < 3) { a0=cmul(a0,w4); a1=cmul(a1,w4); a2=cmul(a2,w4); a3=cmul(a3,w4); }
        }
    }
    __syncthreads();

    if (g != 0) {
        // FUSED S3 fwd (A and B) + pointwise + IS3, all in registers.
        // A position p = 8u + j3 pairs with B position 2047-p = 8(255-u)+(7-j3).
        float2 a8[8], b8[8];
        #pragma unroll
        for (int e = 0; e < 8; e++) {
            a8[e] = smA[PAD(8*u + e)];
            b8[e] = smB[PAD(8*(255 - u) + e)];
        }
        fft8<false>(a8);
        fft8<false>(b8);
        float2 ya[8];
        #pragma unroll
        for (int j3 = 0; j3 < 8; j3++) ya[j3] = pw(a8[j3], b8[7 - j3]);
        fft8<true>(ya);
        #pragma unroll
        for (int e = 0; e < 8; e++) smA[PAD(8*u + e)] = ya[e];
    } else {
        // g==0: S3 forward both rows (in place per thread block-of-8)
        #pragma unroll
        for (int r = 0; r < 2; r++) {
            float2* sm = r ? smB : smA;
            float2 s8[8];
            #pragma unroll
            for (int e = 0; e < 8; e++) s8[e] = sm[PAD(8*u + e)];
            fft8<false>(s8);
            #pragma unroll
            for (int j3 = 0; j3 < 8; j3++) sm[PAD(8*u + j3)] = s8[j3];
        }
        __syncthreads();
        // row 0: pairs k2 <-> (2048-k2) mod 2048 (explicit POS16)
        #pragma unroll
        for (int e = 0; e < 4; e++) {
            int k2 = 4*u + e;                    // 0..1023
            int pa = POS16(k2);
            int pb = POS16((2048 - k2) & 2047);
            float2 Za = smA[PAD(pa)];
            float2 Zb = smA[PAD(pb)];
            float2 Y = pw(Za, Zb);
            smA[PAD(pa)] = Y;
            smA[PAD(pb)] = cconj(Y);
        }
        if (u == 0) {                            // k2 = 1024 self-pair
            int pa = POS16(1024);
            float2 Za = smA[PAD(pa)];
            smA[PAD(pa)] = pw(Za, Za);
        }
        // row 32: position-local p <-> 2047-p
        #pragma unroll
        for (int e = 0; e < 4; e++) {
            int p = 4*u + e;                     // 0..1023
            float2 Za = smB[PAD(p)];
            float2 Zb = smB[PAD(2047 - p)];
            float2 Y = pw(Za, Zb);
            smB[PAD(p)]        = Y;
            smB[PAD(2047 - p)] = cconj(Y);
        }
        __syncthreads();
        // IS3 both rows
        #pragma unroll
        for (int r = 0; r < 2; r++) {
            float2* sm = r ? smB : smA;
            float2 s8[8];
            #pragma unroll
            for (int j3 = 0; j3 < 8; j3++) s8[j3] = sm[PAD(8*u + j3)];
            fft8<true>(s8);
            #pragma unroll
            for (int e = 0; e < 8; e++) sm[PAD(8*u + e)] = s8[e];
        }
    }
    __syncthreads();

    const int rI = u >> 7, idxI = u & 127;
    const bool act = (rI == 0) || (g == 0);
    float2* smI = rI ? smB : smA;
    const int rowI = rI ? rowB : rowA;

    // ---- IS2: conj twiddle W_128^{-e*j2} (input side), inverse radix-16 ----
    // In-place safe: writes have low3 bits == e, only read by the same thread.
    if (act) {
        const int j = idxI >> 3, e = idxI & 7;
        const int base = 128*j + e;
        float2 w1 = twidc(64, e);
        float2 w2 = cmul(w1, w1), w3 = cmul(w2, w1), w4 = cmul(w2, w2);
        v[0] = smI[PAD(base)];
        v[1] = cmul(smI[PAD(base + 8*1)], w1);
        v[2] = cmul(smI[PAD(base + 8*2)], w2);
        v[3] = cmul(smI[PAD(base + 8*3)], w3);
        float2 a0 = w4, a1 = cmul(w1, w4), a2 = cmul(w2, w4), a3 = cmul(w3, w4);
        #pragma unroll
        for (int rr4 = 1; rr4 < 4; rr4++) {
            v[4*rr4+0] = cmul(smI[PAD(base + 8*(4*rr4+0))], a0);
            v[4*rr4+1] = cmul(smI[PAD(base + 8*(4*rr4+1))], a1);
            v[4*rr4+2] = cmul(smI[PAD(base + 8*(4*rr4+2))], a2);
            v[4*rr4+3] = cmul(smI[PAD(base + 8*(4*rr4+3))], a3);
            if (rr4 < 3) { a0=cmul(a0,w4); a1=cmul(a1,w4); a2=cmul(a2,w4); a3=cmul(a3,w4); }
        }
        fft16<true>(v);
        #pragma unroll
        for (int t2 = 0; t2 < 16; t2++) smI[PAD(base + 8*t2)] = v[t2];
    }
    __syncthreads();

    // ---- IS1: conj twiddle W_2048^{-c*j}, inverse radix-16, inter-twiddle
    //      W_N^{-row*(c+128t)} with 1/N folded, store fp16 ----
    if (act) {
        const int c = idxI;
        float2 w1 = twidc(1024, c);
        float2 w2 = cmul(w1, w1), w3 = cmul(w2, w1), w4 = cmul(w2, w2);
        v[0] = smI[PAD(c)];
        v[1] = cmul(smI[PAD(128*1 + c)], w1);
        v[2] = cmul(smI[PAD(128*2 + c)], w2);
        v[3] = cmul(smI[PAD(128*3 + c)], w3);
        float2 a0 = w4, a1 = cmul(w1, w4), a2 = cmul(w2, w4), a3 = cmul(w3, w4);
        #pragma unroll
        for (int rr4 = 1; rr4 < 4; rr4++) {
            v[4*rr4+0] = cmul(smI[PAD(128*(4*rr4+0) + c)], a0);
            v[4*rr4+1] = cmul(smI[PAD(128*(4*rr4+1) + c)], a1);
            v[4*rr4+2] = cmul(smI[PAD(128*(4*rr4+2) + c)], a2);
            v[4*rr4+3] = cmul(smI[PAD(128*(4*rr4+3) + c)], a3);
            if (rr4 < 3) { a0=cmul(a0,w4); a1=cmul(a1,w4); a2=cmul(a2,w4); a3=cmul(a3,w4); }
        }
        fft16<true>(v);
        const float SC = 1.0f / (float)NN;
        float2 b0 = twidc(NHALF, rowI * c);      // rowI*c <= 32*127 < 65536
        b0.x *= SC; b0.y *= SC;
        float2 st  = twidc(NHALF, 128 * rowI);   // <= 4096
        float2 st2 = cmul(st, st), st4 = cmul(st2, st2);
        float2 b1 = cmul(b0, st), b2 = cmul(b0, st2), b3 = cmul(b1, st2);
        __half2* gh = g_h + (size_t)s * (33 * N2) + rowI * N2;
        #pragma unroll
        for (int rr4 = 0; rr4 < 4; rr4++) {
            float2 y0 = cmul(v[4*rr4+0], b0);
            float2 y1 = cmul(v[4*rr4+1], b1);
            float2 y2 = cmul(v[4*rr4+2], b2);
            float2 y3 = cmul(v[4*rr4+3], b3);
            gh[c + 128*(4*rr4+0)] = __floats2half2_rn(y0.x, y0.y);
            gh[c + 128*(4*rr4+1)] = __floats2half2_rn(y1.x, y1.y);
            gh[c + 128*(4*rr4+2)] = __floats2half2_rn(y2.x, y2.y);
            gh[c + 128*(4*rr4+3)] = __floats2half2_rn(y3.x, y3.y);
            if (rr4 < 3) { b0=cmul(b0,st4); b1=cmul(b1,st4); b2=cmul(b2,st4); b3=cmul(b3,st4); }
        }
    }
}

// ---------------------------------------------------------------------------
// Stage 3 (real-output half-size IFFT): per column n2, build
//   G[k] = (U[k] + conj(U[32-k])) + i*w^k*(U[k] - conj(U[32-k])), w=e^{2pi i/64}
// from U rows 0..32 (fp16), then z = IFFT_32(G): y[2n]=Re z[n], y[2n+1]=Im z[n].
// We keep only y[0..31] (causal half) => store z[n] for n < 16 only.
// ---------------------------------------------------------------------------
__global__ void __launch_bounds__(256) k_stage3(float* __restrict__ out) {
    __shared__ float2 sm[32 * 64];
    const int s   = blockIdx.y;
    const int col = threadIdx.x & 63;
    const int m   = threadIdx.x >> 6;            // 0..3
    const int n2  = blockIdx.x * 64 + col;
    const __half2* gh = g_h + (size_t)s * (33 * N2);

    float2 v[8];
    // Build G[m+4t], t=0..7
    #pragma unroll
    for (int t = 0; t < 8; t++) {
        int k = m + 4*t;                         // 0..31
        float2 Uk = __half22float2(gh[k * N2 + n2]);
        float2 Uc = __half22float2(gh[(32 - k) * N2 + n2]);
        Uc.y = -Uc.y;                            // conj(U[32-k])
        float2 sum  = cadd(Uk, Uc);
        float2 diff = csub(Uk, Uc);
        float2 wk = twidc(32, k);                // e^{+2pi i k/64}
        v[t] = cadd(sum, mulpI(cmul(wk, diff))); // sum + i*w^k*diff
    }
    fft8<true>(v);                               // over t -> n0 (natural order)
    // twiddle W_32^{n0*m}, W_32 = e^{+2pi i/32}
    { float2 W[8];
      twpow(W, twidc(16, m));
      #pragma unroll
      for (int n0 = 1; n0 < 8; n0++) v[n0] = cmul(v[n0], W[n0]);
    }
    #pragma unroll
    for (int n0 = 0; n0 < 8; n0++) sm[(n0*4 + m)*64 + col] = v[n0];
    __syncthreads();

    // fft4<inv> over m for n0 in {2q, 2q+1}; keep z[n] only for n < 16
    const int q = m;                             // 0..3
    float* os = out + (size_t)s * T_LEN;
    #pragma unroll
    for (int h2 = 0; h2 < 2; h2++) {
        const int n0 = 2*q + h2;                 // 0..7
        float2 w4[4];
        #pragma unroll
        for (int mm = 0; mm < 4; mm++) w4[mm] = sm[(n0*4 + mm)*64 + col];
        fft4<true>(w4);                          // over m -> s4 ; n = n0 + 8*s4
        #pragma unroll
        for (int s4 = 0; s4 < 2; s4++) {         // n < 16 => y rows < 32 only
            int n = n0 + 8*s4;                   // 0..15
            os[(2*n)     * N2 + n2] = w4[s4].x;  // y[2n]
            os[(2*n + 1) * N2 + n2] = w4[s4].y;  // y[2n+1]
        }
    }
}

extern "C" void kernel_launch(void* const* d_in, const int* in_sizes, int n_in,
                              void* d_out, int out_size) {
    const float* x = (const float*)d_in[0];
    const float* h = (const float*)d_in[1];
    float* out = (float*)d_out;

    k_init_tw<<<NN / 256, 256>>>();
    k_stage1<<<dim3(N2 / 32, SEQ), 256>>>(x, h);
    k_stage2<<<dim3(32, SEQ), 256>>>();
    k_stage3<<<dim3(N2 / 64, SEQ), 256>>>(out);
}